// round 9
// baseline (speedup 1.0000x reference)
#include <cuda_runtime.h>
#include <cuda_bf16.h>
#include <math.h>
#include <stdint.h>

// Problem constants: B=4, Cin=Cout=256, H=W=64, K=3.
#define BATCH 4
#define CIN   256
#define COUT  256
#define HH    64
#define WWID  64
#define NPIX  16384
#define KTOT  2304

// Chunking: 16 channels -> 144 k -> 9 k16 steps per chunk, 16 chunks.
#define CCH    16
#define NSTEP  9
#define NCHUNK 16
#define NGS    (NCHUNK*NSTEP)   // 144 global k16-steps

#define NTHREADS 512            // warps 0-7: GEMM, warps 8-15: builders

// smem: double-buffered B tile, interleaved hi/lo per lane.
// Group (s,nt): 132 u32 (128 payload + 4 pad). 72 groups per buffer.
#define GSTR    132
#define B_WORDS (NSTEP*8*GSTR)          // 9504 u32 per buffer
#define SMEM_BYTES (2*B_WORDS*4)        // 76032 bytes

// Per-pixel scale params.
__device__ float g_f[NPIX];
__device__ int   g_s[NPIX];

// W pre-split into bf16 hi/lo, m16n8k16 A-fragment order:
// layout [gs(144)][half(2)][mt(8)][lane(32)][reg(4)] u32 (bf16x2).
#define WFRAG (NGS*2*8*32*4)            // 294912
__device__ uint32_t g_whi[WFRAG];
__device__ uint32_t g_wlo[WFRAG];

__device__ __forceinline__ unsigned short bf16b(float x) {
    __nv_bfloat16 h = __float2bfloat16(x);
    return *reinterpret_cast<unsigned short*>(&h);
}
__device__ __forceinline__ float bf16f(unsigned short b) {
    __nv_bfloat16 h = *reinterpret_cast<__nv_bfloat16*>(&b);
    return __bfloat162float(h);
}

__device__ __forceinline__ void mma_bf16(float* c, const uint32_t* a, const uint32_t* b) {
    asm volatile(
        "mma.sync.aligned.m16n8k16.row.col.f32.bf16.bf16.f32 "
        "{%0,%1,%2,%3}, {%4,%5,%6,%7}, {%8,%9}, {%0,%1,%2,%3};\n"
        : "+f"(c[0]), "+f"(c[1]), "+f"(c[2]), "+f"(c[3])
        : "r"(a[0]), "r"(a[1]), "r"(a[2]), "r"(a[3]), "r"(b[0]), "r"(b[1]));
}

// ---------------------------------------------------------------------------
// Kernel 0: split W into bf16 hi/lo, m16n8k16 A-fragment order.
// ---------------------------------------------------------------------------
__global__ void adaconv_prep_w(const float* __restrict__ w) {
    int t = blockIdx.x * 256 + threadIdx.x;
    if (t >= WFRAG) return;
    int i    = t & 3;
    int l    = (t >> 2) & 31;
    int mt   = (t >> 7) & 7;
    int half = (t >> 10) & 1;
    int gs   = t >> 11;
    int o = half * 128 + mt * 16 + (l >> 2) + (i & 1) * 8;
    int k = gs * 16 + (l & 3) * 2 + (i >> 1) * 8;
    float v0 = w[(size_t)o * KTOT + k];
    float v1 = w[(size_t)o * KTOT + k + 1];
    unsigned short h0 = bf16b(v0), h1 = bf16b(v1);
    unsigned short l0 = bf16b(v0 - bf16f(h0)), l1 = bf16b(v1 - bf16f(h1));
    g_whi[t] = (uint32_t)h0 | ((uint32_t)h1 << 16);
    g_wlo[t] = (uint32_t)l0 | ((uint32_t)l1 << 16);
}

// ---------------------------------------------------------------------------
// Kernel 1: per-pixel scale params (scrambled-unfold mean).
// ---------------------------------------------------------------------------
__global__ void adaconv_scale_kernel(const float* __restrict__ scales) {
    int pix = blockIdx.x * blockDim.x + threadIdx.x;
    if (pix >= NPIX) return;
    int b  = pix >> 12;
    int r  = (pix >> 6) & 63;
    int wo = pix & 63;
    const float* sb = scales + b * HH * WWID;
    float sum = 0.0f;
#pragma unroll
    for (int jp = 0; jp < 3; jp++) {
        int q  = jp * 64 + r;
        int ho = q / 3;
        int kj = q - 3 * ho;
        int col = wo + kj - 1;
        bool vc = ((unsigned)col < WWID);
#pragma unroll
        for (int ip = 0; ip < 3; ip++) {
            int row = ho + ip - 1;
            if (vc && (unsigned)row < HH)
                sum += sb[row * WWID + col];
        }
    }
    float sm = sum / 9.0f;
    int s = (int)ceilf(sm);
    s = min(3, max(1, s));
    g_f[pix] = sm / (float)s;
    g_s[pix] = s;
}

// ---------------------------------------------------------------------------
// Kernel 2: warp-specialized fused patch-build + bf16-split mma.sync GEMM.
// Block: 128 Cout (half) x 64 px (one row). 512 threads:
//   warps 0-7  : GEMM, m-tile = warp id, A frags from gmem (L2-resident)
//   warps 8-15 : builders, double-buffered B in smem
// Iteration c: GEMM(c) on buf[c&1] || build(c+1) into buf[(c+1)&1]; one sync.
// ---------------------------------------------------------------------------
extern "C" __global__ void __launch_bounds__(NTHREADS, 2)
adaconv_main_kernel(const float* __restrict__ x,
                    const float* __restrict__ bias,
                    float* __restrict__ out) {
    extern __shared__ uint32_t uB[];            // 2 x B_WORDS

    const int tid  = threadIdx.x;
    const int bh   = blockIdx.x;                // b*64 + r
    const int b    = bh >> 6;
    const int r    = bh & 63;
    const int half = blockIdx.y;
    const int o0   = half * 128;
    const bool is_gemm = (tid < 256);

    const float* xb = x + ((size_t)b * CIN << 12);

    // ================= builder state =================
    int   toff[3][3];
    float tmask[3][3];
    float f = 0.0f, gg = 0.0f;
    int   p = 0, cg = 0, nt_b = 0, prow = 0;
    if (!is_gemm) {
        int t2 = tid - 256;
        p    = t2 & 63;
        cg   = t2 >> 6;                         // 0..3
        nt_b = p >> 3;
        prow = (p & 7) << 4;
        int gpix = bh * WWID + p;
        f = g_f[gpix];
        int sc = g_s[gpix];
        gg = 1.0f - f;
#pragma unroll
        for (int jp = 0; jp < 3; jp++) {
            int q  = jp * 64 + r;
            int ho = q / 3;
            int kj = q - 3 * ho;
            int col = p + (kj - 1) * sc;
            bool vc = ((unsigned)col < WWID);
            int colc = min(max(col, 0), WWID - 1);
#pragma unroll
            for (int ip = 0; ip < 3; ip++) {
                int row = ho + (ip - 1) * sc;
                bool v = vc && ((unsigned)row < HH);
                int rowc = min(max(row, 0), HH - 1);
                toff[ip][jp]  = rowc * WWID + colc;
                tmask[ip][jp] = v ? 1.0f : 0.0f;
            }
        }
    }

    // ================= GEMM state =================
    const int w = tid >> 5;                     // warp id = m-tile (0..7)
    const int l = tid & 31;
    float acc[8][4];
    if (is_gemm) {
#pragma unroll
        for (int nt = 0; nt < 8; nt++)
#pragma unroll
            for (int q = 0; q < 4; q++) acc[nt][q] = 0.0f;
    }
    const int aoff = half * 1024 + w * 128 + l * 4;

    // ---- builder routine (inlined twice below) ----
#define BUILD_CHUNK(CHUNK, BUF)                                                \
    do {                                                                       \
        uint32_t* dst = uB + (BUF) * B_WORDS;                                  \
        _Pragma("unroll")                                                      \
        for (int m = 0; m < 2; m++) {                                          \
            int cpair = cg + 4 * m;                                            \
            float v[18];                                                       \
            _Pragma("unroll")                                                  \
            for (int cc = 0; cc < 2; cc++) {                                   \
                int ch = 2 * cpair + cc;                                       \
                const float* xc = xb + ((size_t)((CHUNK) * CCH + ch) << 12);   \
                float t[3][3];                                                 \
                _Pragma("unroll")                                              \
                for (int ip = 0; ip < 3; ip++)                                 \
                    _Pragma("unroll")                                          \
                    for (int jp = 0; jp < 3; jp++)                             \
                        t[ip][jp] = xc[toff[ip][jp]] * tmask[ip][jp];          \
                float u[3][3];                                                 \
                _Pragma("unroll")                                              \
                for (int ip = 0; ip < 3; ip++) {                               \
                    u[ip][0] = f * t[ip][0] + gg * t[ip][1];                   \
                    u[ip][1] = t[ip][1];                                       \
                    u[ip][2] = gg * t[ip][1] + f * t[ip][2];                   \
                }                                                              \
                float* vd = v + cc * 9;                                        \
                _Pragma("unroll")                                              \
                for (int j = 0; j < 3; j++) {                                  \
                    vd[j]     = f * u[0][j] + gg * u[1][j];                    \
                    vd[3 + j] = u[1][j];                                       \
                    vd[6 + j] = gg * u[1][j] + f * u[2][j];                    \
                }                                                              \
            }                                                                  \
            _Pragma("unroll")                                                  \
            for (int j = 0; j < 9; j++) {                                      \
                int k  = 18 * cpair + 2 * j;                                   \
                int s  = k >> 4;                                               \
                int pp = (k & 15) >> 1;                                        \
                int off = (s * 8 + nt_b) * GSTR + prow                         \
                        + ((pp & 3) << 2) + (pp >> 2);                         \
                float v0 = v[2 * j], v1 = v[2 * j + 1];                        \
                unsigned short h0 = bf16b(v0), h1 = bf16b(v1);                 \
                dst[off]     = (uint32_t)h0 | ((uint32_t)h1 << 16);            \
                dst[off + 2] = (uint32_t)bf16b(v0 - bf16f(h0))                 \
                             | ((uint32_t)bf16b(v1 - bf16f(h1)) << 16);        \
            }                                                                  \
        }                                                                      \
    } while (0)

    // ---- prologue: build chunk 0 into buffer 0 ----
    if (!is_gemm) { BUILD_CHUNK(0, 0); }
    __syncthreads();

    // ---- main pipeline ----
    for (int c = 0; c < NCHUNK; c++) {
        if (is_gemm) {
            const uint32_t* bufR = uB + (c & 1) * B_WORDS;
#pragma unroll 3
            for (int s = 0; s < NSTEP; s++) {
                int seg = (c * NSTEP + s) * 2048 + aoff;
                uint4 ah = *(const uint4*)(g_whi + seg);
                uint4 al = *(const uint4*)(g_wlo + seg);
                uint32_t ahi[4] = {ah.x, ah.y, ah.z, ah.w};
                uint32_t alo[4] = {al.x, al.y, al.z, al.w};
#pragma unroll
                for (int nt = 0; nt < 8; nt++) {
                    uint4 bb = *(const uint4*)&bufR[(s * 8 + nt) * GSTR + l * 4];
                    uint32_t bhi[2] = {bb.x, bb.y};
                    uint32_t blo[2] = {bb.z, bb.w};
                    mma_bf16(acc[nt], ahi, bhi);
                    mma_bf16(acc[nt], ahi, blo);
                    mma_bf16(acc[nt], alo, bhi);
                }
            }
        } else if (c + 1 < NCHUNK) {
            BUILD_CHUNK(c + 1, (c + 1) & 1);
        }
        __syncthreads();
    }

    // ---- epilogue (GEMM warps only) ----
    if (is_gemm) {
        int row0 = o0 + w * 16 + (l >> 2);
        int row1 = row0 + 8;
        float bz0 = bias[row0];
        float bz1 = bias[row1];
        size_t base0 = (((size_t)b * COUT + row0) * HH + r) * WWID;
        size_t base1 = (((size_t)b * COUT + row1) * HH + r) * WWID;
#pragma unroll
        for (int nt = 0; nt < 8; nt++) {
            int col = nt * 8 + 2 * (l & 3);
            float2 v0 = {acc[nt][0] + bz0, acc[nt][1] + bz0};
            float2 v1 = {acc[nt][2] + bz1, acc[nt][3] + bz1};
            *(float2*)&out[base0 + col] = v0;
            *(float2*)&out[base1 + col] = v1;
        }
    }
}

// ---------------------------------------------------------------------------
// Entry point. Inputs by element count: x 4194304, scales 16384,
// weight 589824, bias 256. Output fp32.
// ---------------------------------------------------------------------------
extern "C" void kernel_launch(void* const* d_in, const int* in_sizes, int n_in,
                              void* d_out, int out_size) {
    const float *x = 0, *scales = 0, *weight = 0, *bias = 0;
    for (int i = 0; i < n_in; i++) {
        switch (in_sizes[i]) {
            case 4194304: x      = (const float*)d_in[i]; break;
            case 16384:   scales = (const float*)d_in[i]; break;
            case 589824:  weight = (const float*)d_in[i]; break;
            case 256:     bias   = (const float*)d_in[i]; break;
        }
    }
    float* out = (float*)d_out;

    cudaFuncSetAttribute(adaconv_main_kernel,
                         cudaFuncAttributeMaxDynamicSharedMemorySize, SMEM_BYTES);

    adaconv_prep_w<<<(WFRAG + 255) / 256, 256>>>(weight);
    adaconv_scale_kernel<<<NPIX / 256, 256>>>(scales);

    dim3 grid(BATCH * HH, 2);                   // 512 blocks
    adaconv_main_kernel<<<grid, NTHREADS, SMEM_BYTES>>>(x, bias, out);
}

// round 11
// speedup vs baseline: 1.6804x; 1.6804x over previous
#include <cuda_runtime.h>
#include <cuda_fp16.h>
#include <math.h>
#include <stdint.h>

// Problem constants: B=4, Cin=Cout=256, H=W=64, K=3.
#define BATCH 4
#define CIN   256
#define COUT  256
#define HH    64
#define WWID  64
#define NPIX  16384
#define KTOT  2304

// Chunking: 16 channels -> 144 k -> 9 k16 steps per chunk, 16 chunks.
#define CCH    16
#define NSTEP  9
#define NCHUNK 16
#define NGS    (NCHUNK*NSTEP)   // 144 global k16-steps

#define NTHREADS 256

// smem: B tile (single fp16), group (s,nt) = 64 payload + 2 pad u32.
#define GSTR   66
#define B_WORDS (NSTEP*8*GSTR)          // 4752
#define OFF_SF  (B_WORDS)
#define OFF_SSC (OFF_SF + 64)
#define SMEM_WORDS (OFF_SSC + 64)       // 4880
#define SMEM_BYTES (SMEM_WORDS*4)       // 19520

// Per-pixel scale params.
__device__ float g_f[NPIX];
__device__ int   g_s[NPIX];

// W pre-split into fp16 hi/lo, m16n8k16 A-fragment order:
// layout [gs(144)][half(2)][mt(8)][lane(32)][reg(4)] u32 (fp16x2).
#define WFRAG (NGS*2*8*32*4)            // 294912
__device__ uint32_t g_whi[WFRAG];
__device__ uint32_t g_wlo[WFRAG];

__device__ __forceinline__ unsigned short f16b(float x) {
    __half h = __float2half_rn(x);
    return *reinterpret_cast<unsigned short*>(&h);
}
__device__ __forceinline__ float f16f(unsigned short b) {
    __half h = *reinterpret_cast<__half*>(&b);
    return __half2float(h);
}

__device__ __forceinline__ void mma_f16(float* c, const uint32_t* a, const uint32_t* b) {
    asm volatile(
        "mma.sync.aligned.m16n8k16.row.col.f32.f16.f16.f32 "
        "{%0,%1,%2,%3}, {%4,%5,%6,%7}, {%8,%9}, {%0,%1,%2,%3};\n"
        : "+f"(c[0]), "+f"(c[1]), "+f"(c[2]), "+f"(c[3])
        : "r"(a[0]), "r"(a[1]), "r"(a[2]), "r"(a[3]), "r"(b[0]), "r"(b[1]));
}

// ---------------------------------------------------------------------------
// Kernel 0: split W into fp16 hi/lo, m16n8k16 A-fragment order.
// ---------------------------------------------------------------------------
__global__ void adaconv_prep_w(const float* __restrict__ w) {
    int t = blockIdx.x * 256 + threadIdx.x;
    if (t >= WFRAG) return;
    int i    = t & 3;
    int l    = (t >> 2) & 31;
    int mt   = (t >> 7) & 7;
    int half = (t >> 10) & 1;
    int gs   = t >> 11;
    int o = half * 128 + mt * 16 + (l >> 2) + (i & 1) * 8;
    int k = gs * 16 + (l & 3) * 2 + (i >> 1) * 8;
    float v0 = w[(size_t)o * KTOT + k];
    float v1 = w[(size_t)o * KTOT + k + 1];
    unsigned short h0 = f16b(v0), h1 = f16b(v1);
    unsigned short l0 = f16b(v0 - f16f(h0)), l1 = f16b(v1 - f16f(h1));
    g_whi[t] = (uint32_t)h0 | ((uint32_t)h1 << 16);
    g_wlo[t] = (uint32_t)l0 | ((uint32_t)l1 << 16);
}

// ---------------------------------------------------------------------------
// Kernel 1: per-pixel scale params (scrambled-unfold mean).
// ---------------------------------------------------------------------------
__global__ void adaconv_scale_kernel(const float* __restrict__ scales) {
    int pix = blockIdx.x * blockDim.x + threadIdx.x;
    if (pix >= NPIX) return;
    int b  = pix >> 12;
    int r  = (pix >> 6) & 63;
    int wo = pix & 63;
    const float* sb = scales + b * HH * WWID;
    float sum = 0.0f;
#pragma unroll
    for (int jp = 0; jp < 3; jp++) {
        int q  = jp * 64 + r;
        int ho = q / 3;
        int kj = q - 3 * ho;
        int col = wo + kj - 1;
        bool vc = ((unsigned)col < WWID);
#pragma unroll
        for (int ip = 0; ip < 3; ip++) {
            int row = ho + ip - 1;
            if (vc && (unsigned)row < HH)
                sum += sb[row * WWID + col];
        }
    }
    float sm = sum / 9.0f;
    int s = (int)ceilf(sm);
    s = min(3, max(1, s));
    g_f[pix] = sm / (float)s;
    g_s[pix] = s;
}

// ---------------------------------------------------------------------------
// Kernel 2: fused patch-build + fp16-split mma.sync GEMM (2 MMAs per step).
// Block: 128 Cout (half) x 64 px (one row). 256 threads, 8 warps, 1 m-tile/warp.
// A fragments (W hi/lo) from gmem (L2-resident). B: single fp16 in smem.
// ---------------------------------------------------------------------------
extern "C" __global__ void __launch_bounds__(NTHREADS, 2)
adaconv_main_kernel(const float* __restrict__ x,
                    const float* __restrict__ bias,
                    float* __restrict__ out) {
    extern __shared__ uint32_t uB[];
    float* sF  = (float*)(uB + OFF_SF);
    int*   sSc = (int*)(uB + OFF_SSC);

    const int tid  = threadIdx.x;
    const int bh   = blockIdx.x;                // b*64 + r
    const int b    = bh >> 6;
    const int r    = bh & 63;
    const int half = blockIdx.y;
    const int o0   = half * 128;

    if (tid < 64) {
        int pix = bh * WWID + tid;
        sF[tid]  = g_f[pix];
        sSc[tid] = g_s[pix];
    }
    __syncthreads();

    // ---- per-pixel tap geometry: thread builds pixel p, channel-pairs cg+4m ----
    const int p    = tid & 63;
    const int cg   = tid >> 6;                  // 0..3
    const int nt_b = p >> 3;
    const int prow = (p & 7) << 3;              // 8 words per pixel per group
    float f, gg;
    int   toff[3][3];
    float tmask[3][3];
    {
        float ff = sF[p];
        int   sc = sSc[p];
        f = ff; gg = 1.0f - ff;
#pragma unroll
        for (int jp = 0; jp < 3; jp++) {
            int q  = jp * 64 + r;
            int ho = q / 3;
            int kj = q - 3 * ho;
            int col = p + (kj - 1) * sc;
            bool vc = ((unsigned)col < WWID);
            int colc = min(max(col, 0), WWID - 1);
#pragma unroll
            for (int ip = 0; ip < 3; ip++) {
                int row = ho + (ip - 1) * sc;
                bool v = vc && ((unsigned)row < HH);
                int rowc = min(max(row, 0), HH - 1);
                toff[ip][jp]  = rowc * WWID + colc;
                tmask[ip][jp] = v ? 1.0f : 0.0f;
            }
        }
    }

    const int w = tid >> 5;                     // warp id = m-tile
    const int l = tid & 31;

    float acc[8][4];
#pragma unroll
    for (int nt = 0; nt < 8; nt++)
#pragma unroll
        for (int q = 0; q < 4; q++) acc[nt][q] = 0.0f;

    const float* xb = x + ((size_t)b * CIN << 12);
    const int aoff = half * 1024 + w * 128 + l * 4;   // within a gs segment

    for (int chunk = 0; chunk < NCHUNK; chunk++) {
        __syncthreads();                        // prior MMA reads done

        // ---- build B chunk: 2 channel-pairs per thread, single fp16 ----
#pragma unroll
        for (int m = 0; m < 2; m++) {
            int cpair = cg + 4 * m;             // 0..7
            float v[18];
#pragma unroll
            for (int cc = 0; cc < 2; cc++) {
                int c = 2 * cpair + cc;
                const float* xc = xb + ((size_t)(chunk * CCH + c) << 12);
                float t[3][3];
#pragma unroll
                for (int ip = 0; ip < 3; ip++)
#pragma unroll
                    for (int jp = 0; jp < 3; jp++)
                        t[ip][jp] = xc[toff[ip][jp]] * tmask[ip][jp];
                float u[3][3];
#pragma unroll
                for (int ip = 0; ip < 3; ip++) {
                    u[ip][0] = f * t[ip][0] + gg * t[ip][1];
                    u[ip][1] = t[ip][1];
                    u[ip][2] = gg * t[ip][1] + f * t[ip][2];
                }
                float* vd = v + cc * 9;
#pragma unroll
                for (int j = 0; j < 3; j++) {
                    vd[j]     = f * u[0][j] + gg * u[1][j];
                    vd[3 + j] = u[1][j];
                    vd[6 + j] = gg * u[1][j] + f * u[2][j];
                }
            }
            // 9 word-pairs: k = 18*cpair + 2j (even). Frag addr:
            //   pp = (k&15)>>1, addr = group + 8n + 2*(pp&3) + (pp>>2)
#pragma unroll
            for (int j = 0; j < 9; j++) {
                int k  = 18 * cpair + 2 * j;
                int s  = k >> 4;
                int pp = (k & 15) >> 1;
                int off = (s * 8 + nt_b) * GSTR + prow + ((pp & 3) << 1) + (pp >> 2);
                uB[off] = (uint32_t)f16b(v[2 * j])
                        | ((uint32_t)f16b(v[2 * j + 1]) << 16);
            }
        }

        __syncthreads();

        // ---- GEMM over 9 k16-steps: 2 MMAs (W_hi, W_lo) per n-tile ----
#pragma unroll 3
        for (int s = 0; s < NSTEP; s++) {
            int seg = (chunk * NSTEP + s) * 2048 + aoff;
            uint4 ah = *(const uint4*)(g_whi + seg);
            uint4 al = *(const uint4*)(g_wlo + seg);
            uint32_t ahi[4] = {ah.x, ah.y, ah.z, ah.w};
            uint32_t alo[4] = {al.x, al.y, al.z, al.w};
#pragma unroll
            for (int nt = 0; nt < 8; nt++) {
                uint2 bb = *(const uint2*)&uB[(s * 8 + nt) * GSTR + l * 2];
                uint32_t bf[2] = {bb.x, bb.y};
                mma_f16(acc[nt], ahi, bf);
                mma_f16(acc[nt], alo, bf);
            }
        }
    }

    // ---- epilogue ----
    {
        int row0 = o0 + w * 16 + (l >> 2);
        int row1 = row0 + 8;
        float bz0 = bias[row0];
        float bz1 = bias[row1];
        size_t base0 = (((size_t)b * COUT + row0) * HH + r) * WWID;
        size_t base1 = (((size_t)b * COUT + row1) * HH + r) * WWID;
#pragma unroll
        for (int nt = 0; nt < 8; nt++) {
            int col = nt * 8 + 2 * (l & 3);
            float2 v0 = {acc[nt][0] + bz0, acc[nt][1] + bz0};
            float2 v1 = {acc[nt][2] + bz1, acc[nt][3] + bz1};
            *(float2*)&out[base0 + col] = v0;
            *(float2*)&out[base1 + col] = v1;
        }
    }
}

// ---------------------------------------------------------------------------
// Entry point. Inputs by element count: x 4194304, scales 16384,
// weight 589824, bias 256. Output fp32.
// ---------------------------------------------------------------------------
extern "C" void kernel_launch(void* const* d_in, const int* in_sizes, int n_in,
                              void* d_out, int out_size) {
    const float *x = 0, *scales = 0, *weight = 0, *bias = 0;
    for (int i = 0; i < n_in; i++) {
        switch (in_sizes[i]) {
            case 4194304: x      = (const float*)d_in[i]; break;
            case 16384:   scales = (const float*)d_in[i]; break;
            case 589824:  weight = (const float*)d_in[i]; break;
            case 256:     bias   = (const float*)d_in[i]; break;
        }
    }
    float* out = (float*)d_out;

    cudaFuncSetAttribute(adaconv_main_kernel,
                         cudaFuncAttributeMaxDynamicSharedMemorySize, SMEM_BYTES);

    adaconv_prep_w<<<(WFRAG + 255) / 256, 256>>>(weight);
    adaconv_scale_kernel<<<NPIX / 256, 256>>>(scales);

    dim3 grid(BATCH * HH, 2);                   // 512 blocks
    adaconv_main_kernel<<<grid, NTHREADS, SMEM_BYTES>>>(x, bias, out);
}

// round 12
// speedup vs baseline: 2.4190x; 1.4395x over previous
#include <cuda_runtime.h>
#include <cuda_fp16.h>
#include <math.h>
#include <stdint.h>

// Problem constants: B=4, Cin=Cout=256, H=W=64, K=3.
#define BATCH 4
#define CIN   256
#define COUT  256
#define HH    64
#define WWID  64
#define NPIX  16384
#define KTOT  2304

// Chunking: 16 channels -> 144 k -> 9 k16 steps per chunk, 16 chunks.
#define CCH    16
#define NSTEP  9
#define NCHUNK 16
#define NGS    (NCHUNK*NSTEP)   // 144 global k16-steps

#define NTHREADS 512            // 16 warps: m-tile = warp id (M=256)

// smem: B tile (single fp16), group (s,nt) = 64 payload + 2 pad u32.
#define GSTR   66
#define B_WORDS (NSTEP*8*GSTR)          // 4752
#define OFF_SF  (B_WORDS)
#define OFF_SSC (OFF_SF + 64)
#define SMEM_WORDS (OFF_SSC + 64)       // 4880
#define SMEM_BYTES (SMEM_WORDS*4)       // 19520

// Per-pixel scale params.
__device__ float g_f[NPIX];
__device__ int   g_s[NPIX];

// W as single fp16, m16n8k16 A-fragment order:
// layout [gs(144)][mt(16)][lane(32)][reg(4)] u32 (fp16x2).
#define WFRAG (NGS*16*32*4)             // 294912
__device__ uint32_t g_whi[WFRAG];

__device__ __forceinline__ unsigned short f16b(float x) {
    __half h = __float2half_rn(x);
    return *reinterpret_cast<unsigned short*>(&h);
}

__device__ __forceinline__ void mma_f16(float* c, const uint32_t* a, const uint32_t* b) {
    asm volatile(
        "mma.sync.aligned.m16n8k16.row.col.f32.f16.f16.f32 "
        "{%0,%1,%2,%3}, {%4,%5,%6,%7}, {%8,%9}, {%0,%1,%2,%3};\n"
        : "+f"(c[0]), "+f"(c[1]), "+f"(c[2]), "+f"(c[3])
        : "r"(a[0]), "r"(a[1]), "r"(a[2]), "r"(a[3]), "r"(b[0]), "r"(b[1]));
}

// ---------------------------------------------------------------------------
// Kernel 0: W -> fp16, m16n8k16 A-fragment order.
// ---------------------------------------------------------------------------
__global__ void adaconv_prep_w(const float* __restrict__ w) {
    int t = blockIdx.x * 256 + threadIdx.x;
    if (t >= WFRAG) return;
    int i  = t & 3;
    int l  = (t >> 2) & 31;
    int mt = (t >> 7) & 15;
    int gs = t >> 11;
    int o = mt * 16 + (l >> 2) + (i & 1) * 8;
    int k = gs * 16 + (l & 3) * 2 + (i >> 1) * 8;
    float v0 = w[(size_t)o * KTOT + k];
    float v1 = w[(size_t)o * KTOT + k + 1];
    g_whi[t] = (uint32_t)f16b(v0) | ((uint32_t)f16b(v1) << 16);
}

// ---------------------------------------------------------------------------
// Kernel 1: per-pixel scale params (scrambled-unfold mean).
// ---------------------------------------------------------------------------
__global__ void adaconv_scale_kernel(const float* __restrict__ scales) {
    int pix = blockIdx.x * blockDim.x + threadIdx.x;
    if (pix >= NPIX) return;
    int b  = pix >> 12;
    int r  = (pix >> 6) & 63;
    int wo = pix & 63;
    const float* sb = scales + b * HH * WWID;
    float sum = 0.0f;
#pragma unroll
    for (int jp = 0; jp < 3; jp++) {
        int q  = jp * 64 + r;
        int ho = q / 3;
        int kj = q - 3 * ho;
        int col = wo + kj - 1;
        bool vc = ((unsigned)col < WWID);
#pragma unroll
        for (int ip = 0; ip < 3; ip++) {
            int row = ho + ip - 1;
            if (vc && (unsigned)row < HH)
                sum += sb[row * WWID + col];
        }
    }
    float sm = sum / 9.0f;
    int s = (int)ceilf(sm);
    s = min(3, max(1, s));
    g_f[pix] = sm / (float)s;
    g_s[pix] = s;
}

// ---------------------------------------------------------------------------
// Kernel 2: fused patch-build + fp16 mma.sync GEMM (1 MMA per step/nt).
// Block: M=256 (all Cout) x 64 px (one row). 512 threads, 16 warps.
// Warp w = m-tile w (rows w*16..w*16+15). Builder thread: pixel tid&63,
// channel-pair tid>>6 (exactly one per thread). B single fp16 in smem.
// ---------------------------------------------------------------------------
extern "C" __global__ void __launch_bounds__(NTHREADS, 2)
adaconv_main_kernel(const float* __restrict__ x,
                    const float* __restrict__ bias,
                    float* __restrict__ out) {
    extern __shared__ uint32_t uB[];
    float* sF  = (float*)(uB + OFF_SF);
    int*   sSc = (int*)(uB + OFF_SSC);

    const int tid = threadIdx.x;
    const int bh  = blockIdx.x;                 // b*64 + r
    const int b   = bh >> 6;
    const int r   = bh & 63;

    if (tid < 64) {
        int pix = bh * WWID + tid;
        sF[tid]  = g_f[pix];
        sSc[tid] = g_s[pix];
    }
    __syncthreads();

    // ---- per-pixel tap geometry: thread builds pixel p, channel-pair cpair ----
    const int p     = tid & 63;
    const int cpair = tid >> 6;                 // 0..7
    const int nt_b  = p >> 3;
    const int prow  = (p & 7) << 3;             // 8 words per pixel per group
    float f, gg;
    int   toff[3][3];
    float tmask[3][3];
    {
        float ff = sF[p];
        int   sc = sSc[p];
        f = ff; gg = 1.0f - ff;
#pragma unroll
        for (int jp = 0; jp < 3; jp++) {
            int q  = jp * 64 + r;
            int ho = q / 3;
            int kj = q - 3 * ho;
            int col = p + (kj - 1) * sc;
            bool vc = ((unsigned)col < WWID);
            int colc = min(max(col, 0), WWID - 1);
#pragma unroll
            for (int ip = 0; ip < 3; ip++) {
                int row = ho + (ip - 1) * sc;
                bool v = vc && ((unsigned)row < HH);
                int rowc = min(max(row, 0), HH - 1);
                toff[ip][jp]  = rowc * WWID + colc;
                tmask[ip][jp] = v ? 1.0f : 0.0f;
            }
        }
    }

    const int w = tid >> 5;                     // warp id = m-tile (0..15)
    const int l = tid & 31;

    float acc[8][4];
#pragma unroll
    for (int nt = 0; nt < 8; nt++)
#pragma unroll
        for (int q = 0; q < 4; q++) acc[nt][q] = 0.0f;

    const float* xb = x + ((size_t)b * CIN << 12);
    const int aoff = w * 128 + l * 4;           // within a gs segment (2048 words)

    for (int chunk = 0; chunk < NCHUNK; chunk++) {
        __syncthreads();                        // prior MMA reads done

        // ---- build B chunk: exactly one channel-pair per thread ----
        {
            float v[18];
#pragma unroll
            for (int cc = 0; cc < 2; cc++) {
                int c = 2 * cpair + cc;
                const float* xc = xb + ((size_t)(chunk * CCH + c) << 12);
                float t[3][3];
#pragma unroll
                for (int ip = 0; ip < 3; ip++)
#pragma unroll
                    for (int jp = 0; jp < 3; jp++)
                        t[ip][jp] = xc[toff[ip][jp]] * tmask[ip][jp];
                float u[3][3];
#pragma unroll
                for (int ip = 0; ip < 3; ip++) {
                    u[ip][0] = f * t[ip][0] + gg * t[ip][1];
                    u[ip][1] = t[ip][1];
                    u[ip][2] = gg * t[ip][1] + f * t[ip][2];
                }
                float* vd = v + cc * 9;
#pragma unroll
                for (int j = 0; j < 3; j++) {
                    vd[j]     = f * u[0][j] + gg * u[1][j];
                    vd[3 + j] = u[1][j];
                    vd[6 + j] = gg * u[1][j] + f * u[2][j];
                }
            }
            // 9 word-pairs: k = 18*cpair + 2j (even). Frag addr:
            //   pp = (k&15)>>1, addr = group + 8n + 2*(pp&3) + (pp>>2)
#pragma unroll
            for (int j = 0; j < 9; j++) {
                int k  = 18 * cpair + 2 * j;
                int s  = k >> 4;
                int pp = (k & 15) >> 1;
                int off = (s * 8 + nt_b) * GSTR + prow + ((pp & 3) << 1) + (pp >> 2);
                uB[off] = (uint32_t)f16b(v[2 * j])
                        | ((uint32_t)f16b(v[2 * j + 1]) << 16);
            }
        }

        __syncthreads();

        // ---- GEMM over 9 k16-steps: 1 MMA per n-tile ----
#pragma unroll 3
        for (int s = 0; s < NSTEP; s++) {
            int seg = (chunk * NSTEP + s) * 2048 + aoff;
            uint4 ah = *(const uint4*)(g_whi + seg);
            uint32_t ahi[4] = {ah.x, ah.y, ah.z, ah.w};
#pragma unroll
            for (int nt = 0; nt < 8; nt++) {
                uint2 bb = *(const uint2*)&uB[(s * 8 + nt) * GSTR + l * 2];
                uint32_t bf[2] = {bb.x, bb.y};
                mma_f16(acc[nt], ahi, bf);
            }
        }
    }

    // ---- epilogue ----
    {
        int row0 = w * 16 + (l >> 2);
        int row1 = row0 + 8;
        float bz0 = bias[row0];
        float bz1 = bias[row1];
        size_t base0 = (((size_t)b * COUT + row0) * HH + r) * WWID;
        size_t base1 = (((size_t)b * COUT + row1) * HH + r) * WWID;
#pragma unroll
        for (int nt = 0; nt < 8; nt++) {
            int col = nt * 8 + 2 * (l & 3);
            float2 v0 = {acc[nt][0] + bz0, acc[nt][1] + bz0};
            float2 v1 = {acc[nt][2] + bz1, acc[nt][3] + bz1};
            *(float2*)&out[base0 + col] = v0;
            *(float2*)&out[base1 + col] = v1;
        }
    }
}

// ---------------------------------------------------------------------------
// Entry point. Inputs by element count: x 4194304, scales 16384,
// weight 589824, bias 256. Output fp32.
// ---------------------------------------------------------------------------
extern "C" void kernel_launch(void* const* d_in, const int* in_sizes, int n_in,
                              void* d_out, int out_size) {
    const float *x = 0, *scales = 0, *weight = 0, *bias = 0;
    for (int i = 0; i < n_in; i++) {
        switch (in_sizes[i]) {
            case 4194304: x      = (const float*)d_in[i]; break;
            case 16384:   scales = (const float*)d_in[i]; break;
            case 589824:  weight = (const float*)d_in[i]; break;
            case 256:     bias   = (const float*)d_in[i]; break;
        }
    }
    float* out = (float*)d_out;

    cudaFuncSetAttribute(adaconv_main_kernel,
                         cudaFuncAttributeMaxDynamicSharedMemorySize, SMEM_BYTES);

    adaconv_prep_w<<<(WFRAG + 255) / 256, 256>>>(weight);
    adaconv_scale_kernel<<<NPIX / 256, 256>>>(scales);

    dim3 grid(BATCH * HH);                      // 256 blocks, single wave
    adaconv_main_kernel<<<grid, NTHREADS, SMEM_BYTES>>>(x, bias, out);
}

// round 13
// speedup vs baseline: 2.5972x; 1.0737x over previous
#include <cuda_runtime.h>
#include <cuda_fp16.h>
#include <math.h>
#include <stdint.h>

// Problem constants: B=4, Cin=Cout=256, H=W=64, K=3.
#define BATCH 4
#define CIN   256
#define COUT  256
#define HH    64
#define WWID  64
#define NPIX  16384
#define KTOT  2304

// Chunking: 16 channels -> 144 k -> 9 k16 steps per chunk, 16 chunks.
#define CCH    16
#define NSTEP  9
#define NCHUNK 16
#define NGS    (NCHUNK*NSTEP)   // 144 global k16-steps

#define NTHREADS 512            // 16 warps: m-tile = warp id (M=256)

// smem: double-buffered B tile (single fp16), group (s,nt) = 64+2 pad u32.
#define GSTR   66
#define B_WORDS (NSTEP*8*GSTR)          // 4752 u32 per buffer
#define SMEM_BYTES (2*B_WORDS*4)        // 38016

// W as single fp16, m16n8k16 A-fragment order:
// layout [gs(144)][mt(16)][lane(32)][reg(4)] u32 (fp16x2).
#define WFRAG (NGS*16*32*4)             // 294912
__device__ uint32_t g_whi[WFRAG];

__device__ __forceinline__ unsigned short f16b(float x) {
    __half h = __float2half_rn(x);
    return *reinterpret_cast<unsigned short*>(&h);
}

__device__ __forceinline__ void mma_f16(float* c, const uint32_t* a, const uint32_t* b) {
    asm volatile(
        "mma.sync.aligned.m16n8k16.row.col.f32.f16.f16.f32 "
        "{%0,%1,%2,%3}, {%4,%5,%6,%7}, {%8,%9}, {%0,%1,%2,%3};\n"
        : "+f"(c[0]), "+f"(c[1]), "+f"(c[2]), "+f"(c[3])
        : "r"(a[0]), "r"(a[1]), "r"(a[2]), "r"(a[3]), "r"(b[0]), "r"(b[1]));
}

// ---------------------------------------------------------------------------
// Kernel 0: W -> fp16, m16n8k16 A-fragment order.
// ---------------------------------------------------------------------------
__global__ void adaconv_prep_w(const float* __restrict__ w) {
    int t = blockIdx.x * 256 + threadIdx.x;
    if (t >= WFRAG) return;
    int i  = t & 3;
    int l  = (t >> 2) & 31;
    int mt = (t >> 7) & 15;
    int gs = t >> 11;
    int o = mt * 16 + (l >> 2) + (i & 1) * 8;
    int k = gs * 16 + (l & 3) * 2 + (i >> 1) * 8;
    float v0 = w[(size_t)o * KTOT + k];
    float v1 = w[(size_t)o * KTOT + k + 1];
    g_whi[t] = (uint32_t)f16b(v0) | ((uint32_t)f16b(v1) << 16);
}

// ---------------------------------------------------------------------------
// Kernel 1: fused scale + patch-build + fp16 mma.sync GEMM.
// Block: M=256 (all Cout) x 64 px (one row). 512 threads, 16 warps.
// Warp w = m-tile w. Builder thread: pixel tid&63, channel-pair tid>>6.
// B double-buffered in smem; per chunk: MMA(c) || build(c+1) -> one sync.
// ---------------------------------------------------------------------------
extern "C" __global__ void __launch_bounds__(NTHREADS, 2)
adaconv_main_kernel(const float* __restrict__ x,
                    const float* __restrict__ scales,
                    const float* __restrict__ bias,
                    float* __restrict__ out) {
    extern __shared__ uint32_t uB[];            // 2 x B_WORDS

    const int tid = threadIdx.x;
    const int bh  = blockIdx.x;                 // b*64 + r
    const int b   = bh >> 6;
    const int r   = bh & 63;

    // ---- per-pixel scale params (computed inline; 8x redundant, cached) ----
    const int p     = tid & 63;
    const int cpair = tid >> 6;                 // 0..7
    const int nt_b  = p >> 3;
    const int prow  = (p & 7) << 3;             // 8 words per pixel per group
    float f, gg;
    int   sc;
    {
        const float* sb = scales + b * HH * WWID;
        float sum = 0.0f;
#pragma unroll
        for (int jp = 0; jp < 3; jp++) {
            int q  = jp * 64 + r;
            int ho = q / 3;
            int kj = q - 3 * ho;
            int col = p + kj - 1;
            bool vc = ((unsigned)col < WWID);
#pragma unroll
            for (int ip = 0; ip < 3; ip++) {
                int row = ho + ip - 1;
                if (vc && (unsigned)row < HH)
                    sum += sb[row * WWID + col];
            }
        }
        float sm = sum / 9.0f;
        sc = (int)ceilf(sm);
        sc = min(3, max(1, sc));
        f  = sm / (float)sc;
        gg = 1.0f - f;
    }

    // ---- per-pixel tap geometry ----
    int   toff[3][3];
    float tmask[3][3];
#pragma unroll
    for (int jp = 0; jp < 3; jp++) {
        int q  = jp * 64 + r;
        int ho = q / 3;
        int kj = q - 3 * ho;
        int col = p + (kj - 1) * sc;
        bool vc = ((unsigned)col < WWID);
        int colc = min(max(col, 0), WWID - 1);
#pragma unroll
        for (int ip = 0; ip < 3; ip++) {
            int row = ho + (ip - 1) * sc;
            bool v = vc && ((unsigned)row < HH);
            int rowc = min(max(row, 0), HH - 1);
            toff[ip][jp]  = rowc * WWID + colc;
            tmask[ip][jp] = v ? 1.0f : 0.0f;
        }
    }

    const int w = tid >> 5;                     // warp id = m-tile (0..15)
    const int l = tid & 31;

    float acc[8][4];
#pragma unroll
    for (int nt = 0; nt < 8; nt++)
#pragma unroll
        for (int q = 0; q < 4; q++) acc[nt][q] = 0.0f;

    const float* xb = x + ((size_t)b * CIN << 12);
    const int aoff = w * 128 + l * 4;           // within a gs segment (2048 words)

    // ---- builder: one channel-pair per thread into the given buffer ----
    auto build = [&](int chunk, uint32_t* dst) {
        float v[18];
#pragma unroll
        for (int cc = 0; cc < 2; cc++) {
            int c = 2 * cpair + cc;
            const float* xc = xb + ((size_t)(chunk * CCH + c) << 12);
            float t[3][3];
#pragma unroll
            for (int ip = 0; ip < 3; ip++)
#pragma unroll
                for (int jp = 0; jp < 3; jp++)
                    t[ip][jp] = xc[toff[ip][jp]] * tmask[ip][jp];
            float u[3][3];
#pragma unroll
            for (int ip = 0; ip < 3; ip++) {
                u[ip][0] = f * t[ip][0] + gg * t[ip][1];
                u[ip][1] = t[ip][1];
                u[ip][2] = gg * t[ip][1] + f * t[ip][2];
            }
            float* vd = v + cc * 9;
#pragma unroll
            for (int j = 0; j < 3; j++) {
                vd[j]     = f * u[0][j] + gg * u[1][j];
                vd[3 + j] = u[1][j];
                vd[6 + j] = gg * u[1][j] + f * u[2][j];
            }
        }
        // 9 word-pairs: k = 18*cpair + 2j (even). Frag addr:
        //   pp = (k&15)>>1, addr = group + 8n + 2*(pp&3) + (pp>>2)
#pragma unroll
        for (int j = 0; j < 9; j++) {
            int k  = 18 * cpair + 2 * j;
            int s  = k >> 4;
            int pp = (k & 15) >> 1;
            int off = (s * 8 + nt_b) * GSTR + prow + ((pp & 3) << 1) + (pp >> 2);
            dst[off] = (uint32_t)f16b(v[2 * j])
                     | ((uint32_t)f16b(v[2 * j + 1]) << 16);
        }
    };

    // ---- prologue: build chunk 0 into buffer 0 ----
    build(0, uB);
    __syncthreads();

    // ---- main pipeline: MMA(c) then build(c+1) into the other buffer ----
    for (int chunk = 0; chunk < NCHUNK; chunk++) {
        const uint32_t* bufR = uB + (chunk & 1) * B_WORDS;
#pragma unroll 3
        for (int s = 0; s < NSTEP; s++) {
            int seg = (chunk * NSTEP + s) * 2048 + aoff;
            uint4 ah = *(const uint4*)(g_whi + seg);
            uint32_t ahi[4] = {ah.x, ah.y, ah.z, ah.w};
#pragma unroll
            for (int nt = 0; nt < 8; nt++) {
                uint2 bb = *(const uint2*)&bufR[(s * 8 + nt) * GSTR + l * 2];
                uint32_t bf[2] = {bb.x, bb.y};
                mma_f16(acc[nt], ahi, bf);
            }
        }
        if (chunk + 1 < NCHUNK)
            build(chunk + 1, uB + ((chunk + 1) & 1) * B_WORDS);
        __syncthreads();
    }

    // ---- epilogue ----
    {
        int row0 = w * 16 + (l >> 2);
        int row1 = row0 + 8;
        float bz0 = bias[row0];
        float bz1 = bias[row1];
        size_t base0 = (((size_t)b * COUT + row0) * HH + r) * WWID;
        size_t base1 = (((size_t)b * COUT + row1) * HH + r) * WWID;
#pragma unroll
        for (int nt = 0; nt < 8; nt++) {
            int col = nt * 8 + 2 * (l & 3);
            float2 v0 = {acc[nt][0] + bz0, acc[nt][1] + bz0};
            float2 v1 = {acc[nt][2] + bz1, acc[nt][3] + bz1};
            *(float2*)&out[base0 + col] = v0;
            *(float2*)&out[base1 + col] = v1;
        }
    }
}

// ---------------------------------------------------------------------------
// Entry point. Inputs by element count: x 4194304, scales 16384,
// weight 589824, bias 256. Output fp32.
// ---------------------------------------------------------------------------
extern "C" void kernel_launch(void* const* d_in, const int* in_sizes, int n_in,
                              void* d_out, int out_size) {
    const float *x = 0, *scales = 0, *weight = 0, *bias = 0;
    for (int i = 0; i < n_in; i++) {
        switch (in_sizes[i]) {
            case 4194304: x      = (const float*)d_in[i]; break;
            case 16384:   scales = (const float*)d_in[i]; break;
            case 589824:  weight = (const float*)d_in[i]; break;
            case 256:     bias   = (const float*)d_in[i]; break;
        }
    }
    float* out = (float*)d_out;

    cudaFuncSetAttribute(adaconv_main_kernel,
                         cudaFuncAttributeMaxDynamicSharedMemorySize, SMEM_BYTES);

    adaconv_prep_w<<<(WFRAG + 255) / 256, 256>>>(weight);

    dim3 grid(BATCH * HH);                      // 256 blocks
    adaconv_main_kernel<<<grid, NTHREADS, SMEM_BYTES>>>(x, scales, bias, out);
}